// round 9
// baseline (speedup 1.0000x reference)
#include <cuda_runtime.h>
#include <cuda_bf16.h>
#include <cstdint>

// Problem constants (fixed by the dataset)
#define N_NODES 25000
#define N_EDGES 400000
#define F_DIM   128
#define S_DIM   256
#define L_DIM   64
#define ROUNDS  4
#define MT      196                 // ceil(25000 / 128)
#define MPAD    (MT * 128)          // 25088
#define NBLK    98                  // ceil(25000 / 256)

// ---------------------------------------------------------------------------
// Scratch (device globals; no allocation anywhere)
// ---------------------------------------------------------------------------
__device__ __align__(256) float g_state[(size_t)N_NODES * S_DIM];        // 25.6 MB
__device__ __align__(256) float g_PQ[(size_t)MPAD * 512];                // 51.4 MB
__device__ __align__(256) __nv_bfloat16 g_Ah[(size_t)MPAD * S_DIM];      // state hi
__device__ __align__(256) __nv_bfloat16 g_Al[(size_t)MPAD * S_DIM];      // state lo
__device__ __align__(256) __nv_bfloat16 g_Xh[(size_t)MPAD * F_DIM];      // x hi
__device__ __align__(256) __nv_bfloat16 g_Xl[(size_t)MPAD * F_DIM];      // x lo
__device__ __align__(256) __nv_bfloat16 g_Wc_h[(size_t)ROUNDS * 512 * S_DIM];
__device__ __align__(256) __nv_bfloat16 g_Wc_l[(size_t)ROUNDS * 512 * S_DIM];
__device__ __align__(256) __nv_bfloat16 g_Wi_h[(size_t)S_DIM * F_DIM];   // [n=256][k=128]
__device__ __align__(256) __nv_bfloat16 g_Wi_l[(size_t)S_DIM * F_DIM];
__device__ __align__(256) __nv_bfloat16 g_Wo_h[(size_t)L_DIM * S_DIM];   // [n=64][k=256]
__device__ __align__(256) __nv_bfloat16 g_Wo_l[(size_t)L_DIM * S_DIM];
__device__ int g_counts[N_NODES];
__device__ int g_row_ptr[N_NODES + 1];
__device__ int g_cursor[N_NODES];
__device__ int g_col_src[N_EDGES];
__device__ int g_blk[128];

// ---------------------------------------------------------------------------
// small helpers
// ---------------------------------------------------------------------------
__device__ __forceinline__ void bf16_split(float x, __nv_bfloat16& h, __nv_bfloat16& l) {
    h = __float2bfloat16(x);
    l = __float2bfloat16(x - __bfloat162float(h));
}
__device__ __forceinline__ uint32_t pack_bf2(__nv_bfloat16 a, __nv_bfloat16 b) {
    return (uint32_t)__bfloat16_as_ushort(a) | ((uint32_t)__bfloat16_as_ushort(b) << 16);
}
__device__ __forceinline__ uint32_t smem_u32(const void* p) {
    return (uint32_t)__cvta_generic_to_shared(p);
}
__device__ __forceinline__ void cp_async16(uint32_t dst, const void* src) {
    asm volatile("cp.async.cg.shared.global [%0], [%1], 16;" :: "r"(dst), "l"(src));
}
__device__ __forceinline__ void cp_commit() {
    asm volatile("cp.async.commit_group;" ::: "memory");
}
__device__ __forceinline__ void cp_wait1() {
    asm volatile("cp.async.wait_group 1;" ::: "memory");
}
__device__ __forceinline__ void cp_wait0() {
    asm volatile("cp.async.wait_group 0;" ::: "memory");
}
#define LDSM_X4(r0, r1, r2, r3, addr)                                          \
    asm volatile("ldmatrix.sync.aligned.m8n8.x4.shared.b16 {%0,%1,%2,%3}, [%4];" \
                 : "=r"(r0), "=r"(r1), "=r"(r2), "=r"(r3) : "r"(addr))
#define MMA_BF16(d, a, b)                                                      \
    asm volatile(                                                              \
        "mma.sync.aligned.m16n8k16.row.col.f32.bf16.bf16.f32 "                 \
        "{%0,%1,%2,%3},{%4,%5,%6,%7},{%8,%9},{%0,%1,%2,%3};"                   \
        : "+f"((d)[0]), "+f"((d)[1]), "+f"((d)[2]), "+f"((d)[3])               \
        : "r"((a)[0]), "r"((a)[1]), "r"((a)[2]), "r"((a)[3]),                  \
          "r"((b)[0]), "r"((b)[1]))

// ---------------------------------------------------------------------------
// CSR construction
// ---------------------------------------------------------------------------
__global__ void hist_kernel(const int* __restrict__ dest) {
    int e = blockIdx.x * blockDim.x + threadIdx.x;
    if (e < N_EDGES) atomicAdd(&g_counts[dest[e]], 1);
}
__global__ void __launch_bounds__(256) scan1_kernel() {
    __shared__ int temp[256];
    const int tx = threadIdx.x;
    const int i  = blockIdx.x * 256 + tx;
    int v = (i < N_NODES) ? g_counts[i] : 0;
    temp[tx] = v;
    __syncthreads();
#pragma unroll
    for (int off = 1; off < 256; off <<= 1) {
        int t = (tx >= off) ? temp[tx - off] : 0;
        __syncthreads();
        temp[tx] += t;
        __syncthreads();
    }
    if (i < N_NODES) g_cursor[i] = temp[tx];     // local inclusive prefix (temp use)
    if (tx == 255) g_blk[blockIdx.x] = temp[255];
}
__global__ void __launch_bounds__(128) scan2_kernel() {
    __shared__ int temp[128];
    const int tx = threadIdx.x;
    int v = (tx < NBLK) ? g_blk[tx] : 0;
    temp[tx] = v;
    __syncthreads();
#pragma unroll
    for (int off = 1; off < 128; off <<= 1) {
        int t = (tx >= off) ? temp[tx - off] : 0;
        __syncthreads();
        temp[tx] += t;
        __syncthreads();
    }
    if (tx < NBLK) g_blk[tx] = temp[tx] - v;     // exclusive block offset
}
__global__ void __launch_bounds__(256) scan3_kernel() {
    const int i = blockIdx.x * 256 + threadIdx.x;
    if (i < N_NODES) {
        int incl = g_cursor[i] + g_blk[blockIdx.x];
        g_row_ptr[i + 1] = incl;
        g_cursor[i]      = incl - g_counts[i];
    }
    if (i == 0) g_row_ptr[0] = 0;
}
__global__ void fill_kernel(const int* __restrict__ src, const int* __restrict__ dest) {
    int e = blockIdx.x * blockDim.x + threadIdx.x;
    if (e < N_EDGES) {
        int d   = dest[e];
        int pos = atomicAdd(&g_cursor[d], 1);
        g_col_src[pos] = src[e];
    }
}

// ---------------------------------------------------------------------------
// Fused split-conversions + counts zeroing: one kernel, sectioned grid.
//   [0, 12544)        convX   : MPAD*128 elems
//   [12544, 14592)    convWcat: 4*512*256 elems
//   [14592, 14720)    convW_in: 256*128 elems   ([n][k] from [k][n])
//   [14720, 14784)    convW_out: 64*256 elems
//   [14784, 14882)    zero g_counts
// ---------------------------------------------------------------------------
#define CONV_BLOCKS (14784 + NBLK)
__global__ void __launch_bounds__(256) conv_all_kernel(
    const float* __restrict__ x, const float* __restrict__ W_msg,
    const float* __restrict__ W_in, const float* __restrict__ W_out)
{
    const int b = blockIdx.x;
    __nv_bfloat16 h, l;
    if (b < 12544) {                       // convX
        int idx = b * 256 + threadIdx.x;
        int row = idx >> 7;
        float v = (row < N_NODES) ? x[idx] : 0.f;
        bf16_split(v, h, l);
        g_Xh[idx] = h;
        g_Xl[idx] = l;
    } else if (b < 14592) {                // convWcat
        int idx = (b - 12544) * 256 + threadIdx.x;
        int k  = idx & 255;
        int rn = idx >> 8;
        int n  = rn & 511;
        int r  = rn >> 9;
        const float* Wr = W_msg + (size_t)r * 512 * 256;
        float v = (n < 256) ? Wr[(size_t)k * 256 + n]
                            : Wr[(size_t)(256 + k) * 256 + (n - 256)];
        bf16_split(v, h, l);
        g_Wc_h[idx] = h;
        g_Wc_l[idx] = l;
    } else if (b < 14720) {                // convW_in [K=128,N=256] -> [n][k]
        int idx = (b - 14592) * 256 + threadIdx.x;
        int n = idx >> 7, k = idx & 127;
        bf16_split(W_in[(size_t)k * 256 + n], h, l);
        g_Wi_h[idx] = h;
        g_Wi_l[idx] = l;
    } else if (b < 14784) {                // convW_out [K=256,N=64] -> [n][k]
        int idx = (b - 14720) * 256 + threadIdx.x;
        int n = idx >> 8, k = idx & 255;
        bf16_split(W_out[(size_t)k * 64 + n], h, l);
        g_Wo_h[idx] = h;
        g_Wo_l[idx] = l;
    } else {                               // zero g_counts
        int idx = (b - 14784) * 256 + threadIdx.x;
        if (idx < N_NODES) g_counts[idx] = 0;
    }
}

// ---------------------------------------------------------------------------
// 3x-bf16 emulated fp32 GEMM on mma.sync.m16n8k16:
//   C[M, (ny0+gy)*BN] = A[M,K] @ B^T  where B given [N,K] row-major.
//   Products along K': (Ah,Bh), (Al,Bh), (Ah,Bl).
// BM=128, BK=64, BN template, 256 thr = 8 warps (4x2), warp tile 32 x BN/2.
// 3-stage cp.async pipeline, ONE __syncthreads per K-chunk.
// MINB: min blocks/SM for launch_bounds (3 for BN=64 -> 24 warps/SM).
// ---------------------------------------------------------------------------
template <int BN, int MINB, bool RELU, bool BIAS, bool EMIT>
__global__ void __launch_bounds__(256, MINB) gemm3_kernel(
    const __nv_bfloat16* __restrict__ Ah, const __nv_bfloat16* __restrict__ Al,
    const __nv_bfloat16* __restrict__ Bh, const __nv_bfloat16* __restrict__ Bl,
    const float* __restrict__ bias, float* __restrict__ C,
    int M, int K, int ldc, int ny0)
{
    constexpr int A_BYTES = 128 * 128;          // 128 rows x 64 bf16
    constexpr int B_BYTES = BN * 128;
    constexpr int NI = BN / 16;
    constexpr int NJ = BN / 32;

    extern __shared__ __align__(128) char smem[];
    const uint32_t sb = smem_u32(smem);
    const uint32_t sA[3] = {sb, sb + A_BYTES, sb + 2 * A_BYTES};
    const uint32_t sB[3] = {sb + 3 * A_BYTES,
                            sb + 3 * A_BYTES + B_BYTES,
                            sb + 3 * A_BYTES + 2 * B_BYTES};

    const int tid  = threadIdx.x;
    const int lane = tid & 31;
    const int warp = tid >> 5;
    const int wm   = warp & 3;
    const int wn   = warp >> 2;
    const int bm   = blockIdx.x * 128;
    const int ny   = blockIdx.y + ny0;

    const int nK = K >> 6;
    const int T  = 3 * nK;                      // >= 6 always

    float acc[2][NI][4];
#pragma unroll
    for (int i = 0; i < 2; i++)
#pragma unroll
        for (int j = 0; j < NI; j++)
#pragma unroll
            for (int t = 0; t < 4; t++) acc[i][j][t] = 0.f;

    auto load_tiles = [&](int it, int buf) {
        const int p = it / nK;
        const int c = it - p * nK;
        const __nv_bfloat16* As = (p == 1) ? Al : Ah;
        const __nv_bfloat16* Bs = (p == 2) ? Bl : Bh;
        const int koff = c * 64;
#pragma unroll
        for (int i = 0; i < 4; i++) {
            int id  = tid + i * 256;
            int row = id >> 3, ch = id & 7;
            const void* src = As + (size_t)(bm + row) * K + koff + ch * 8;
            cp_async16(sA[buf] + row * 128 + ((ch ^ (row & 7)) << 4), src);
        }
#pragma unroll
        for (int i = 0; i < (BN * 8) / 256; i++) {
            int id  = tid + i * 256;
            int row = id >> 3, ch = id & 7;
            const void* src = Bs + (size_t)(ny * BN + row) * K + koff + ch * 8;
            cp_async16(sB[buf] + row * 128 + ((ch ^ (row & 7)) << 4), src);
        }
        cp_commit();
    };

    load_tiles(0, 0);
    load_tiles(1, 1);
    int buf = 0;
    for (int it = 0; it < T; it++) {
        if (it < T - 1) cp_wait1(); else cp_wait0();
        __syncthreads();
        if (it + 2 < T) load_tiles(it + 2, (it + 2) % 3);

#pragma unroll
        for (int ks = 0; ks < 4; ks++) {
            const int chunk = ks * 2 + (lane >> 4);
            uint32_t a[2][4];
#pragma unroll
            for (int mi = 0; mi < 2; mi++) {
                int row = wm * 32 + mi * 16 + (lane & 15);
                uint32_t ad = sA[buf] + row * 128 + ((chunk ^ (row & 7)) << 4);
                LDSM_X4(a[mi][0], a[mi][1], a[mi][2], a[mi][3], ad);
            }
            uint32_t b[NI][2];
#pragma unroll
            for (int nj = 0; nj < NJ; nj++) {
                int row = wn * (BN / 2) + nj * 16 + (lane & 15);
                uint32_t bd = sB[buf] + row * 128 + ((chunk ^ (row & 7)) << 4);
                uint32_t m0, m1, m2, m3;
                LDSM_X4(m0, m1, m2, m3, bd);
                b[nj * 2 + 0][0] = m0; b[nj * 2 + 0][1] = m2;
                b[nj * 2 + 1][0] = m1; b[nj * 2 + 1][1] = m3;
            }
#pragma unroll
            for (int mi = 0; mi < 2; mi++)
#pragma unroll
                for (int nif = 0; nif < NI; nif++)
                    MMA_BF16(acc[mi][nif], a[mi], b[nif]);
        }
        buf = (buf + 1 == 3) ? 0 : buf + 1;
    }

    // ---- epilogue ----
#pragma unroll
    for (int mi = 0; mi < 2; mi++) {
        const int r0 = bm + wm * 32 + mi * 16 + (lane >> 2);
#pragma unroll
        for (int nif = 0; nif < NI; nif++) {
            const int col = ny * BN + wn * (BN / 2) + nif * 8 + (lane & 3) * 2;
            float b0v = BIAS ? bias[col]     : 0.f;
            float b1v = BIAS ? bias[col + 1] : 0.f;
#pragma unroll
            for (int h = 0; h < 2; h++) {
                const int r = r0 + h * 8;
                if (r < M) {
                    float v0 = acc[mi][nif][h * 2 + 0] + b0v;
                    float v1 = acc[mi][nif][h * 2 + 1] + b1v;
                    if (RELU) { v0 = fmaxf(v0, 0.f); v1 = fmaxf(v1, 0.f); }
                    *(float2*)(C + (size_t)r * ldc + col) = make_float2(v0, v1);
                    if (EMIT) {
                        __nv_bfloat16 h0, l0, h1, l1;
                        bf16_split(v0, h0, l0);
                        bf16_split(v1, h1, l1);
                        const size_t u = ((size_t)r * 256 + col) >> 1;
                        ((uint32_t*)g_Ah)[u] = pack_bf2(h0, h1);
                        ((uint32_t*)g_Al)[u] = pack_bf2(l0, l1);
                    }
                }
            }
        }
    }
}

// ---------------------------------------------------------------------------
// Fused message + segment-sum + state update + bf16 split emission.
//   state[n] += sum_{e in in(n)} relu(P[src[e]] + Q[n] + b)
// 2 nodes per 128-thread block; 64 threads x 4 channels (float4) per node.
// PQ row = [P(256) | Q(256)] fp32, stride 512 (= 128 float4).
// ---------------------------------------------------------------------------
__global__ void __launch_bounds__(128) aggregate_kernel(const float* __restrict__ bias) {
    const int n  = blockIdx.x * 2 + (threadIdx.x >> 6);
    const int tx = threadIdx.x & 63;      // float4 channel group
    const int c  = tx * 4;

    const int beg = g_row_ptr[n];
    const int end = g_row_ptr[n + 1];

    const float4* PQ4 = (const float4*)g_PQ;     // row stride = 128 float4
    const float4  qv  = PQ4[(size_t)n * 128 + 64 + tx];
    const float4  bv  = *(const float4*)(bias + c);
    const float q0 = qv.x + bv.x;
    const float q1 = qv.y + bv.y;
    const float q2 = qv.z + bv.z;
    const float q3 = qv.w + bv.w;

    const size_t nofs = (size_t)n * S_DIM + c;
    float4 a = *(const float4*)(g_state + nofs);

    int e = beg;
    for (; e + 4 <= end; e += 4) {
        int s0 = g_col_src[e + 0];
        int s1 = g_col_src[e + 1];
        int s2 = g_col_src[e + 2];
        int s3 = g_col_src[e + 3];
        float4 p0 = PQ4[(size_t)s0 * 128 + tx];
        float4 p1 = PQ4[(size_t)s1 * 128 + tx];
        float4 p2 = PQ4[(size_t)s2 * 128 + tx];
        float4 p3 = PQ4[(size_t)s3 * 128 + tx];
        a.x += fmaxf(p0.x + q0, 0.f); a.y += fmaxf(p0.y + q1, 0.f);
        a.z += fmaxf(p0.z + q2, 0.f); a.w += fmaxf(p0.w + q3, 0.f);
        a.x += fmaxf(p1.x + q0, 0.f); a.y += fmaxf(p1.y + q1, 0.f);
        a.z += fmaxf(p1.z + q2, 0.f); a.w += fmaxf(p1.w + q3, 0.f);
        a.x += fmaxf(p2.x + q0, 0.f); a.y += fmaxf(p2.y + q1, 0.f);
        a.z += fmaxf(p2.z + q2, 0.f); a.w += fmaxf(p2.w + q3, 0.f);
        a.x += fmaxf(p3.x + q0, 0.f); a.y += fmaxf(p3.y + q1, 0.f);
        a.z += fmaxf(p3.z + q2, 0.f); a.w += fmaxf(p3.w + q3, 0.f);
    }
    for (; e < end; e++) {
        int s = g_col_src[e];
        float4 p = PQ4[(size_t)s * 128 + tx];
        a.x += fmaxf(p.x + q0, 0.f); a.y += fmaxf(p.y + q1, 0.f);
        a.z += fmaxf(p.z + q2, 0.f); a.w += fmaxf(p.w + q3, 0.f);
    }
    *(float4*)(g_state + nofs) = a;

    __nv_bfloat16 h0, l0, h1, l1, h2, l2, h3, l3;
    bf16_split(a.x, h0, l0);
    bf16_split(a.y, h1, l1);
    bf16_split(a.z, h2, l2);
    bf16_split(a.w, h3, l3);
    const size_t u = nofs >> 1;
    ((uint32_t*)g_Ah)[u]     = pack_bf2(h0, h1);
    ((uint32_t*)g_Ah)[u + 1] = pack_bf2(h2, h3);
    ((uint32_t*)g_Al)[u]     = pack_bf2(l0, l1);
    ((uint32_t*)g_Al)[u + 1] = pack_bf2(l2, l3);
}

// ---------------------------------------------------------------------------
// Launch
// ---------------------------------------------------------------------------
extern "C" void kernel_launch(void* const* d_in, const int* in_sizes, int n_in,
                              void* d_out, int out_size)
{
    (void)in_sizes; (void)n_in; (void)out_size;

    const float* x          = (const float*)d_in[0];  // [25000,128]
    const int*   edge_index = (const int*)  d_in[1];  // [2,400000]
    const float* W_in  = (const float*)d_in[3];       // [128,256]
    const float* b_in  = (const float*)d_in[4];       // [256]
    const float* W_msg = (const float*)d_in[5];       // [4,512,256]
    const float* b_msg = (const float*)d_in[6];       // [4,256]
    const float* W_out = (const float*)d_in[7];       // [256,64]
    const float* b_out = (const float*)d_in[8];       // [64]
    float* out = (float*)d_out;                       // [25000,64]

    const int* src  = edge_index;
    const int* dest = edge_index + N_EDGES;

    void *p_state, *p_PQ, *p_Ah, *p_Al, *p_Xh, *p_Xl;
    void *p_Wch, *p_Wcl, *p_Wih, *p_Wil, *p_Woh, *p_Wol;
    cudaGetSymbolAddress(&p_state, g_state);
    cudaGetSymbolAddress(&p_PQ, g_PQ);
    cudaGetSymbolAddress(&p_Ah, g_Ah);
    cudaGetSymbolAddress(&p_Al, g_Al);
    cudaGetSymbolAddress(&p_Xh, g_Xh);
    cudaGetSymbolAddress(&p_Xl, g_Xl);
    cudaGetSymbolAddress(&p_Wch, g_Wc_h);
    cudaGetSymbolAddress(&p_Wcl, g_Wc_l);
    cudaGetSymbolAddress(&p_Wih, g_Wi_h);
    cudaGetSymbolAddress(&p_Wil, g_Wi_l);
    cudaGetSymbolAddress(&p_Woh, g_Wo_h);
    cudaGetSymbolAddress(&p_Wol, g_Wo_l);
    float* state = (float*)p_state;
    float* PQ    = (float*)p_PQ;

    const int SMEM_IN = 3 * (128 * 128) + 3 * (128 * 128);  // 98304 (BN=128)
    const int SMEM_R  = 3 * (128 * 128) + 3 * (64 * 128);   // 73728 (BN=64)
    cudaFuncSetAttribute(gemm3_kernel<128, 2, true,  true,  true >,
                         cudaFuncAttributeMaxDynamicSharedMemorySize, SMEM_IN);
    cudaFuncSetAttribute(gemm3_kernel<64, 3, false, false, false>,
                         cudaFuncAttributeMaxDynamicSharedMemorySize, SMEM_R);
    cudaFuncSetAttribute(gemm3_kernel<64, 3, false, true,  false>,
                         cudaFuncAttributeMaxDynamicSharedMemorySize, SMEM_R);

    const int EB = (N_EDGES + 255) / 256;

    // Launch order: indices 3,4,5 are all round-GEMM slices (for ncu capture).
    conv_all_kernel<<<CONV_BLOCKS, 256>>>(x, W_msg, W_in, W_out);       // 0 (+zero)
    gemm3_kernel<128, 2, true, true, true><<<dim3(MT, 2), 256, SMEM_IN>>>( // 1 input
        (__nv_bfloat16*)p_Xh, (__nv_bfloat16*)p_Xl,
        (__nv_bfloat16*)p_Wih, (__nv_bfloat16*)p_Wil,
        b_in, state, N_NODES, F_DIM, 256, 0);
    hist_kernel<<<EB, 256>>>(dest);                                     // 2
    // PQ round 0, split into 3 slices (ny 0-2, 3-5, 6-7)
    gemm3_kernel<64, 3, false, false, false><<<dim3(MT, 3), 256, SMEM_R>>>( // 3
        (__nv_bfloat16*)p_Ah, (__nv_bfloat16*)p_Al,
        (__nv_bfloat16*)p_Wch, (__nv_bfloat16*)p_Wcl,
        nullptr, PQ, N_NODES, S_DIM, 512, 0);
    gemm3_kernel<64, 3, false, false, false><<<dim3(MT, 3), 256, SMEM_R>>>( // 4
        (__nv_bfloat16*)p_Ah, (__nv_bfloat16*)p_Al,
        (__nv_bfloat16*)p_Wch, (__nv_bfloat16*)p_Wcl,
        nullptr, PQ, N_NODES, S_DIM, 512, 3);
    gemm3_kernel<64, 3, false, false, false><<<dim3(MT, 2), 256, SMEM_R>>>( // 5
        (__nv_bfloat16*)p_Ah, (__nv_bfloat16*)p_Al,
        (__nv_bfloat16*)p_Wch, (__nv_bfloat16*)p_Wcl,
        nullptr, PQ, N_NODES, S_DIM, 512, 6);
    scan1_kernel<<<NBLK, 256>>>();                                      // 6
    scan2_kernel<<<1, 128>>>();                                         // 7
    scan3_kernel<<<NBLK, 256>>>();                                      // 8
    fill_kernel<<<EB, 256>>>(src, dest);                                // 9
    aggregate_kernel<<<N_NODES / 2, 128>>>(b_msg);                      // 10

    for (int r = 1; r < ROUNDS; r++) {
        gemm3_kernel<64, 3, false, false, false><<<dim3(MT, 8), 256, SMEM_R>>>(
            (__nv_bfloat16*)p_Ah, (__nv_bfloat16*)p_Al,
            (__nv_bfloat16*)p_Wch + (size_t)r * 512 * S_DIM,
            (__nv_bfloat16*)p_Wcl + (size_t)r * 512 * S_DIM,
            nullptr, PQ, N_NODES, S_DIM, 512, 0);
        aggregate_kernel<<<N_NODES / 2, 128>>>(b_msg + (size_t)r * S_DIM);
    }

    // --- output net: out = state @ W_out + b_out ---
    gemm3_kernel<64, 3, false, true, false><<<dim3(MT, 1), 256, SMEM_R>>>(
        (__nv_bfloat16*)p_Ah, (__nv_bfloat16*)p_Al,
        (__nv_bfloat16*)p_Woh, (__nv_bfloat16*)p_Wol,
        b_out, out, N_NODES, S_DIM, 64, 0);
}

// round 11
// speedup vs baseline: 1.0658x; 1.0658x over previous
#include <cuda_runtime.h>
#include <cuda_bf16.h>
#include <cuda_fp16.h>
#include <cstdint>

// Problem constants (fixed by the dataset)
#define N_NODES 25000
#define N_EDGES 400000
#define F_DIM   128
#define S_DIM   256
#define L_DIM   64
#define ROUNDS  4
#define MT      196                 // ceil(25000 / 128)
#define MPAD    (MT * 128)          // 25088
#define NBLK    98                  // ceil(25000 / 256)

// ---------------------------------------------------------------------------
// Scratch (device globals; no allocation anywhere)
// ---------------------------------------------------------------------------
__device__ __align__(256) float g_state[(size_t)N_NODES * S_DIM];        // 25.6 MB
__device__ __align__(256) __half g_PQ[(size_t)MPAD * 512];               // 25.7 MB (fp16!)
__device__ __align__(256) __nv_bfloat16 g_Ah[(size_t)MPAD * S_DIM];      // state hi
__device__ __align__(256) __nv_bfloat16 g_Al[(size_t)MPAD * S_DIM];      // state lo
__device__ __align__(256) __nv_bfloat16 g_Xh[(size_t)MPAD * F_DIM];      // x hi
__device__ __align__(256) __nv_bfloat16 g_Xl[(size_t)MPAD * F_DIM];      // x lo
__device__ __align__(256) __nv_bfloat16 g_Wc_h[(size_t)ROUNDS * 512 * S_DIM];
__device__ __align__(256) __nv_bfloat16 g_Wc_l[(size_t)ROUNDS * 512 * S_DIM];
__device__ __align__(256) __nv_bfloat16 g_Wi_h[(size_t)S_DIM * F_DIM];   // [n=256][k=128]
__device__ __align__(256) __nv_bfloat16 g_Wi_l[(size_t)S_DIM * F_DIM];
__device__ __align__(256) __nv_bfloat16 g_Wo_h[(size_t)L_DIM * S_DIM];   // [n=64][k=256]
__device__ __align__(256) __nv_bfloat16 g_Wo_l[(size_t)L_DIM * S_DIM];
__device__ int g_counts[N_NODES];
__device__ int g_row_ptr[N_NODES + 1];
__device__ int g_cursor[N_NODES];
__device__ int g_col_src[N_EDGES];
__device__ int g_blk[128];

// ---------------------------------------------------------------------------
// small helpers
// ---------------------------------------------------------------------------
__device__ __forceinline__ void bf16_split(float x, __nv_bfloat16& h, __nv_bfloat16& l) {
    h = __float2bfloat16(x);
    l = __float2bfloat16(x - __bfloat162float(h));
}
__device__ __forceinline__ uint32_t pack_bf2(__nv_bfloat16 a, __nv_bfloat16 b) {
    return (uint32_t)__bfloat16_as_ushort(a) | ((uint32_t)__bfloat16_as_ushort(b) << 16);
}
__device__ __forceinline__ uint32_t smem_u32(const void* p) {
    return (uint32_t)__cvta_generic_to_shared(p);
}
__device__ __forceinline__ void cp_async16(uint32_t dst, const void* src) {
    asm volatile("cp.async.cg.shared.global [%0], [%1], 16;" :: "r"(dst), "l"(src));
}
__device__ __forceinline__ void cp_commit() {
    asm volatile("cp.async.commit_group;" ::: "memory");
}
__device__ __forceinline__ void cp_wait1() {
    asm volatile("cp.async.wait_group 1;" ::: "memory");
}
__device__ __forceinline__ void cp_wait0() {
    asm volatile("cp.async.wait_group 0;" ::: "memory");
}
#define LDSM_X4(r0, r1, r2, r3, addr)                                          \
    asm volatile("ldmatrix.sync.aligned.m8n8.x4.shared.b16 {%0,%1,%2,%3}, [%4];" \
                 : "=r"(r0), "=r"(r1), "=r"(r2), "=r"(r3) : "r"(addr))
#define MMA_BF16(d, a, b)                                                      \
    asm volatile(                                                              \
        "mma.sync.aligned.m16n8k16.row.col.f32.bf16.bf16.f32 "                 \
        "{%0,%1,%2,%3},{%4,%5,%6,%7},{%8,%9},{%0,%1,%2,%3};"                   \
        : "+f"((d)[0]), "+f"((d)[1]), "+f"((d)[2]), "+f"((d)[3])               \
        : "r"((a)[0]), "r"((a)[1]), "r"((a)[2]), "r"((a)[3]),                  \
          "r"((b)[0]), "r"((b)[1]))

// ---------------------------------------------------------------------------
// CSR construction
// ---------------------------------------------------------------------------
__global__ void hist_kernel(const int* __restrict__ dest) {
    int e = blockIdx.x * blockDim.x + threadIdx.x;
    if (e < N_EDGES) atomicAdd(&g_counts[dest[e]], 1);
}
__global__ void __launch_bounds__(256) scan1_kernel() {
    __shared__ int temp[256];
    const int tx = threadIdx.x;
    const int i  = blockIdx.x * 256 + tx;
    int v = (i < N_NODES) ? g_counts[i] : 0;
    temp[tx] = v;
    __syncthreads();
#pragma unroll
    for (int off = 1; off < 256; off <<= 1) {
        int t = (tx >= off) ? temp[tx - off] : 0;
        __syncthreads();
        temp[tx] += t;
        __syncthreads();
    }
    if (i < N_NODES) g_cursor[i] = temp[tx];     // local inclusive prefix (temp use)
    if (tx == 255) g_blk[blockIdx.x] = temp[255];
}
__global__ void __launch_bounds__(128) scan2_kernel() {
    __shared__ int temp[128];
    const int tx = threadIdx.x;
    int v = (tx < NBLK) ? g_blk[tx] : 0;
    temp[tx] = v;
    __syncthreads();
#pragma unroll
    for (int off = 1; off < 128; off <<= 1) {
        int t = (tx >= off) ? temp[tx - off] : 0;
        __syncthreads();
        temp[tx] += t;
        __syncthreads();
    }
    if (tx < NBLK) g_blk[tx] = temp[tx] - v;     // exclusive block offset
}
__global__ void __launch_bounds__(256) scan3_kernel() {
    const int i = blockIdx.x * 256 + threadIdx.x;
    if (i < N_NODES) {
        int incl = g_cursor[i] + g_blk[blockIdx.x];
        g_row_ptr[i + 1] = incl;
        g_cursor[i]      = incl - g_counts[i];
    }
    if (i == 0) g_row_ptr[0] = 0;
}
__global__ void fill_kernel(const int* __restrict__ src, const int* __restrict__ dest) {
    int e = blockIdx.x * blockDim.x + threadIdx.x;
    if (e < N_EDGES) {
        int d   = dest[e];
        int pos = atomicAdd(&g_cursor[d], 1);
        g_col_src[pos] = src[e];
    }
}

// ---------------------------------------------------------------------------
// Fused split-conversions + counts zeroing: one kernel, sectioned grid.
// ---------------------------------------------------------------------------
#define CONV_BLOCKS (14784 + NBLK)
__global__ void __launch_bounds__(256) conv_all_kernel(
    const float* __restrict__ x, const float* __restrict__ W_msg,
    const float* __restrict__ W_in, const float* __restrict__ W_out)
{
    const int b = blockIdx.x;
    __nv_bfloat16 h, l;
    if (b < 12544) {                       // convX
        int idx = b * 256 + threadIdx.x;
        int row = idx >> 7;
        float v = (row < N_NODES) ? x[idx] : 0.f;
        bf16_split(v, h, l);
        g_Xh[idx] = h;
        g_Xl[idx] = l;
    } else if (b < 14592) {                // convWcat
        int idx = (b - 12544) * 256 + threadIdx.x;
        int k  = idx & 255;
        int rn = idx >> 8;
        int n  = rn & 511;
        int r  = rn >> 9;
        const float* Wr = W_msg + (size_t)r * 512 * 256;
        float v = (n < 256) ? Wr[(size_t)k * 256 + n]
                            : Wr[(size_t)(256 + k) * 256 + (n - 256)];
        bf16_split(v, h, l);
        g_Wc_h[idx] = h;
        g_Wc_l[idx] = l;
    } else if (b < 14720) {                // convW_in [K=128,N=256] -> [n][k]
        int idx = (b - 14592) * 256 + threadIdx.x;
        int n = idx >> 7, k = idx & 127;
        bf16_split(W_in[(size_t)k * 256 + n], h, l);
        g_Wi_h[idx] = h;
        g_Wi_l[idx] = l;
    } else if (b < 14784) {                // convW_out [K=256,N=64] -> [n][k]
        int idx = (b - 14720) * 256 + threadIdx.x;
        int n = idx >> 8, k = idx & 255;
        bf16_split(W_out[(size_t)k * 64 + n], h, l);
        g_Wo_h[idx] = h;
        g_Wo_l[idx] = l;
    } else {                               // zero g_counts
        int idx = (b - 14784) * 256 + threadIdx.x;
        if (idx < N_NODES) g_counts[idx] = 0;
    }
}

// ---------------------------------------------------------------------------
// 3x-bf16 emulated fp32 GEMM on mma.sync.m16n8k16:
//   C[M, gy*BN] = A[M,K] @ B^T  where B given [N,K] row-major.
//   Products along K': (Ah,Bh), (Al,Bh), (Ah,Bl).
// BM=128, BK=64, BN template, 256 thr = 8 warps (4x2), warp tile 32 x BN/2.
// 3-stage cp.async pipeline, ONE __syncthreads per K-chunk.
// HALFC: write C as packed fp16 (half2); else fp32.
// ---------------------------------------------------------------------------
template <int BN, int MINB, bool RELU, bool BIAS, bool EMIT, bool HALFC>
__global__ void __launch_bounds__(256, MINB) gemm3_kernel(
    const __nv_bfloat16* __restrict__ Ah, const __nv_bfloat16* __restrict__ Al,
    const __nv_bfloat16* __restrict__ Bh, const __nv_bfloat16* __restrict__ Bl,
    const float* __restrict__ bias, void* __restrict__ Cout,
    int M, int K, int ldc)
{
    constexpr int A_BYTES = 128 * 128;          // 128 rows x 64 bf16
    constexpr int B_BYTES = BN * 128;
    constexpr int NI = BN / 16;
    constexpr int NJ = BN / 32;

    extern __shared__ __align__(128) char smem[];
    const uint32_t sb = smem_u32(smem);
    const uint32_t sA[3] = {sb, sb + A_BYTES, sb + 2 * A_BYTES};
    const uint32_t sB[3] = {sb + 3 * A_BYTES,
                            sb + 3 * A_BYTES + B_BYTES,
                            sb + 3 * A_BYTES + 2 * B_BYTES};

    const int tid  = threadIdx.x;
    const int lane = tid & 31;
    const int warp = tid >> 5;
    const int wm   = warp & 3;
    const int wn   = warp >> 2;
    const int bm   = blockIdx.x * 128;
    const int ny   = blockIdx.y;

    const int nK = K >> 6;
    const int T  = 3 * nK;                      // >= 6 always

    float acc[2][NI][4];
#pragma unroll
    for (int i = 0; i < 2; i++)
#pragma unroll
        for (int j = 0; j < NI; j++)
#pragma unroll
            for (int t = 0; t < 4; t++) acc[i][j][t] = 0.f;

    auto load_tiles = [&](int it, int buf) {
        const int p = it / nK;
        const int c = it - p * nK;
        const __nv_bfloat16* As = (p == 1) ? Al : Ah;
        const __nv_bfloat16* Bs = (p == 2) ? Bl : Bh;
        const int koff = c * 64;
#pragma unroll
        for (int i = 0; i < 4; i++) {
            int id  = tid + i * 256;
            int row = id >> 3, ch = id & 7;
            const void* src = As + (size_t)(bm + row) * K + koff + ch * 8;
            cp_async16(sA[buf] + row * 128 + ((ch ^ (row & 7)) << 4), src);
        }
#pragma unroll
        for (int i = 0; i < (BN * 8) / 256; i++) {
            int id  = tid + i * 256;
            int row = id >> 3, ch = id & 7;
            const void* src = Bs + (size_t)(ny * BN + row) * K + koff + ch * 8;
            cp_async16(sB[buf] + row * 128 + ((ch ^ (row & 7)) << 4), src);
        }
        cp_commit();
    };

    load_tiles(0, 0);
    load_tiles(1, 1);
    int buf = 0;
    for (int it = 0; it < T; it++) {
        if (it < T - 1) cp_wait1(); else cp_wait0();
        __syncthreads();
        if (it + 2 < T) load_tiles(it + 2, (it + 2) % 3);

#pragma unroll
        for (int ks = 0; ks < 4; ks++) {
            const int chunk = ks * 2 + (lane >> 4);
            uint32_t a[2][4];
#pragma unroll
            for (int mi = 0; mi < 2; mi++) {
                int row = wm * 32 + mi * 16 + (lane & 15);
                uint32_t ad = sA[buf] + row * 128 + ((chunk ^ (row & 7)) << 4);
                LDSM_X4(a[mi][0], a[mi][1], a[mi][2], a[mi][3], ad);
            }
            uint32_t b[NI][2];
#pragma unroll
            for (int nj = 0; nj < NJ; nj++) {
                int row = wn * (BN / 2) + nj * 16 + (lane & 15);
                uint32_t bd = sB[buf] + row * 128 + ((chunk ^ (row & 7)) << 4);
                uint32_t m0, m1, m2, m3;
                LDSM_X4(m0, m1, m2, m3, bd);
                b[nj * 2 + 0][0] = m0; b[nj * 2 + 0][1] = m2;
                b[nj * 2 + 1][0] = m1; b[nj * 2 + 1][1] = m3;
            }
#pragma unroll
            for (int mi = 0; mi < 2; mi++)
#pragma unroll
                for (int nif = 0; nif < NI; nif++)
                    MMA_BF16(acc[mi][nif], a[mi], b[nif]);
        }
        buf = (buf + 1 == 3) ? 0 : buf + 1;
    }

    // ---- epilogue ----
#pragma unroll
    for (int mi = 0; mi < 2; mi++) {
        const int r0 = bm + wm * 32 + mi * 16 + (lane >> 2);
#pragma unroll
        for (int nif = 0; nif < NI; nif++) {
            const int col = ny * BN + wn * (BN / 2) + nif * 8 + (lane & 3) * 2;
            float b0v = BIAS ? bias[col]     : 0.f;
            float b1v = BIAS ? bias[col + 1] : 0.f;
#pragma unroll
            for (int h = 0; h < 2; h++) {
                const int r = r0 + h * 8;
                if (r < M) {
                    float v0 = acc[mi][nif][h * 2 + 0] + b0v;
                    float v1 = acc[mi][nif][h * 2 + 1] + b1v;
                    if (RELU) { v0 = fmaxf(v0, 0.f); v1 = fmaxf(v1, 0.f); }
                    if (HALFC) {
                        __half2 hv = __floats2half2_rn(v0, v1);
                        *(__half2*)((__half*)Cout + (size_t)r * ldc + col) = hv;
                    } else {
                        *(float2*)((float*)Cout + (size_t)r * ldc + col) =
                            make_float2(v0, v1);
                    }
                    if (EMIT) {
                        __nv_bfloat16 h0, l0, h1, l1;
                        bf16_split(v0, h0, l0);
                        bf16_split(v1, h1, l1);
                        const size_t u = ((size_t)r * 256 + col) >> 1;
                        ((uint32_t*)g_Ah)[u] = pack_bf2(h0, h1);
                        ((uint32_t*)g_Al)[u] = pack_bf2(l0, l1);
                    }
                }
            }
        }
    }
}

// ---------------------------------------------------------------------------
// Fused message + segment-sum + state update + bf16 split emission.
//   state[n] += sum_{e in in(n)} relu(P[src[e]] + Q[n] + b)
// PQ is fp16: row = [P(256) | Q(256)] half, 512 halves = 1024B -> gather 512B/row.
// 2 nodes per 128-thread block; 64 threads x 4 channels (uint2 = 4 halves).
// ---------------------------------------------------------------------------
__global__ void __launch_bounds__(128) aggregate_kernel(const float* __restrict__ bias) {
    const int n  = blockIdx.x * 2 + (threadIdx.x >> 6);
    const int tx = threadIdx.x & 63;      // 4-half channel group
    const int c  = tx * 4;

    const int beg = g_row_ptr[n];
    const int end = g_row_ptr[n + 1];

    const uint2* PQ2 = (const uint2*)g_PQ;       // row stride = 128 uint2
    const uint2  qr  = PQ2[(size_t)n * 128 + 64 + tx];
    const float2 qa  = __half22float2(*(const __half2*)&qr.x);
    const float2 qb  = __half22float2(*(const __half2*)&qr.y);
    const float4 bv  = *(const float4*)(bias + c);
    const float q0 = qa.x + bv.x;
    const float q1 = qa.y + bv.y;
    const float q2 = qb.x + bv.z;
    const float q3 = qb.y + bv.w;

    const size_t nofs = (size_t)n * S_DIM + c;
    float4 a = *(const float4*)(g_state + nofs);

    int e = beg;
    for (; e + 4 <= end; e += 4) {
        int s0 = g_col_src[e + 0];
        int s1 = g_col_src[e + 1];
        int s2 = g_col_src[e + 2];
        int s3 = g_col_src[e + 3];
        uint2 r0 = PQ2[(size_t)s0 * 128 + tx];
        uint2 r1 = PQ2[(size_t)s1 * 128 + tx];
        uint2 r2 = PQ2[(size_t)s2 * 128 + tx];
        uint2 r3 = PQ2[(size_t)s3 * 128 + tx];
#pragma unroll
        for (int j = 0; j < 4; j++) {
            uint2 rr = (j == 0) ? r0 : (j == 1) ? r1 : (j == 2) ? r2 : r3;
            float2 pa = __half22float2(*(const __half2*)&rr.x);
            float2 pb = __half22float2(*(const __half2*)&rr.y);
            a.x += fmaxf(pa.x + q0, 0.f);
            a.y += fmaxf(pa.y + q1, 0.f);
            a.z += fmaxf(pb.x + q2, 0.f);
            a.w += fmaxf(pb.y + q3, 0.f);
        }
    }
    for (; e < end; e++) {
        int s = g_col_src[e];
        uint2 rr = PQ2[(size_t)s * 128 + tx];
        float2 pa = __half22float2(*(const __half2*)&rr.x);
        float2 pb = __half22float2(*(const __half2*)&rr.y);
        a.x += fmaxf(pa.x + q0, 0.f);
        a.y += fmaxf(pa.y + q1, 0.f);
        a.z += fmaxf(pb.x + q2, 0.f);
        a.w += fmaxf(pb.y + q3, 0.f);
    }
    *(float4*)(g_state + nofs) = a;

    __nv_bfloat16 h0, l0, h1, l1, h2, l2, h3, l3;
    bf16_split(a.x, h0, l0);
    bf16_split(a.y, h1, l1);
    bf16_split(a.z, h2, l2);
    bf16_split(a.w, h3, l3);
    const size_t u = nofs >> 1;
    ((uint32_t*)g_Ah)[u]     = pack_bf2(h0, h1);
    ((uint32_t*)g_Ah)[u + 1] = pack_bf2(h2, h3);
    ((uint32_t*)g_Al)[u]     = pack_bf2(l0, l1);
    ((uint32_t*)g_Al)[u + 1] = pack_bf2(l2, l3);
}

// ---------------------------------------------------------------------------
// Launch
// ---------------------------------------------------------------------------
extern "C" void kernel_launch(void* const* d_in, const int* in_sizes, int n_in,
                              void* d_out, int out_size)
{
    (void)in_sizes; (void)n_in; (void)out_size;

    const float* x          = (const float*)d_in[0];  // [25000,128]
    const int*   edge_index = (const int*)  d_in[1];  // [2,400000]
    const float* W_in  = (const float*)d_in[3];       // [128,256]
    const float* b_in  = (const float*)d_in[4];       // [256]
    const float* W_msg = (const float*)d_in[5];       // [4,512,256]
    const float* b_msg = (const float*)d_in[6];       // [4,256]
    const float* W_out = (const float*)d_in[7];       // [256,64]
    const float* b_out = (const float*)d_in[8];       // [64]
    float* out = (float*)d_out;                       // [25000,64]

    const int* src  = edge_index;
    const int* dest = edge_index + N_EDGES;

    void *p_state, *p_PQ, *p_Ah, *p_Al, *p_Xh, *p_Xl;
    void *p_Wch, *p_Wcl, *p_Wih, *p_Wil, *p_Woh, *p_Wol;
    cudaGetSymbolAddress(&p_state, g_state);
    cudaGetSymbolAddress(&p_PQ, g_PQ);
    cudaGetSymbolAddress(&p_Ah, g_Ah);
    cudaGetSymbolAddress(&p_Al, g_Al);
    cudaGetSymbolAddress(&p_Xh, g_Xh);
    cudaGetSymbolAddress(&p_Xl, g_Xl);
    cudaGetSymbolAddress(&p_Wch, g_Wc_h);
    cudaGetSymbolAddress(&p_Wcl, g_Wc_l);
    cudaGetSymbolAddress(&p_Wih, g_Wi_h);
    cudaGetSymbolAddress(&p_Wil, g_Wi_l);
    cudaGetSymbolAddress(&p_Woh, g_Wo_h);
    cudaGetSymbolAddress(&p_Wol, g_Wo_l);

    const int SMEM_IN = 3 * (128 * 128) + 3 * (128 * 128);  // 98304 (BN=128)
    const int SMEM_O  = 3 * (128 * 128) + 3 * (64 * 128);   // 73728 (BN=64)
    cudaFuncSetAttribute(gemm3_kernel<128, 2, true,  true,  true,  false>,
                         cudaFuncAttributeMaxDynamicSharedMemorySize, SMEM_IN);
    cudaFuncSetAttribute(gemm3_kernel<128, 2, false, false, false, true >,
                         cudaFuncAttributeMaxDynamicSharedMemorySize, SMEM_IN);
    cudaFuncSetAttribute(gemm3_kernel<64,  3, false, true,  false, false>,
                         cudaFuncAttributeMaxDynamicSharedMemorySize, SMEM_O);

    const int EB = (N_EDGES + 255) / 256;

    // Launch order: index 3 (= ncu capture target) is the BN=128 round GEMM.
    conv_all_kernel<<<CONV_BLOCKS, 256>>>(x, W_msg, W_in, W_out);          // 0
    gemm3_kernel<128, 2, true, true, true, false><<<dim3(MT, 2), 256, SMEM_IN>>>( // 1
        (__nv_bfloat16*)p_Xh, (__nv_bfloat16*)p_Xl,
        (__nv_bfloat16*)p_Wih, (__nv_bfloat16*)p_Wil,
        b_in, p_state, N_NODES, F_DIM, 256);
    hist_kernel<<<EB, 256>>>(dest);                                        // 2
    gemm3_kernel<128, 2, false, false, false, true><<<dim3(MT, 4), 256, SMEM_IN>>>( // 3
        (__nv_bfloat16*)p_Ah, (__nv_bfloat16*)p_Al,
        (__nv_bfloat16*)p_Wch, (__nv_bfloat16*)p_Wcl,
        nullptr, p_PQ, N_NODES, S_DIM, 512);
    scan1_kernel<<<NBLK, 256>>>();                                         // 4
    scan2_kernel<<<1, 128>>>();                                            // 5
    scan3_kernel<<<NBLK, 256>>>();                                         // 6
    fill_kernel<<<EB, 256>>>(src, dest);                                   // 7
    aggregate_kernel<<<N_NODES / 2, 128>>>(b_msg);                         // 8

    for (int r = 1; r < ROUNDS; r++) {
        gemm3_kernel<128, 2, false, false, false, true><<<dim3(MT, 4), 256, SMEM_IN>>>(
            (__nv_bfloat16*)p_Ah, (__nv_bfloat16*)p_Al,
            (__nv_bfloat16*)p_Wch + (size_t)r * 512 * S_DIM,
            (__nv_bfloat16*)p_Wcl + (size_t)r * 512 * S_DIM,
            nullptr, p_PQ, N_NODES, S_DIM, 512);
        aggregate_kernel<<<N_NODES / 2, 128>>>(b_msg + (size_t)r * S_DIM);
    }

    // --- output net: out = state @ W_out + b_out ---
    gemm3_kernel<64, 3, false, true, false, false><<<dim3(MT, 1), 256, SMEM_O>>>(
        (__nv_bfloat16*)p_Ah, (__nv_bfloat16*)p_Al,
        (__nv_bfloat16*)p_Woh, (__nv_bfloat16*)p_Wol,
        b_out, out, N_NODES, S_DIM, 64);
}